// round 6
// baseline (speedup 1.0000x reference)
#include <cuda_runtime.h>
#include <cstdint>

#define WINDOW   512
#define PREFIX   16
#define SEQ      4096
#define NH       16
#define BATCH    2
#define DM       1024
#define HD       64

#define NX  ((size_t)BATCH * SEQ * DM)        // 8388608
#define NW1 ((size_t)3 * DM * DM)             // 3145728
#define NW2 ((size_t)DM * DM)                 // 1048576

// Scratch (device globals; allocation APIs are forbidden).
__device__ float g_q[(size_t)BATCH * NH * SEQ * HD];   // tf32, pre-scaled 1/8
__device__ float g_k[(size_t)BATCH * NH * SEQ * HD];   // tf32
__device__ float g_v[(size_t)BATCH * NH * SEQ * HD];   // tf32
__device__ float g_o[(size_t)BATCH * SEQ * DM];        // tf32 [b][s][h*64+d]
__device__ float g_x[NX];                              // tf32 copy of x
__device__ float g_w1[NW1];                            // tf32 copy of w_qkv
__device__ float g_w2[NW2];                            // tf32 copy of w_out

// ---------------------------------------------------------------------------
__device__ __forceinline__ void cp_async16(unsigned smem_dst, const void* gsrc) {
    asm volatile("cp.async.cg.shared.global [%0], [%1], 16;\n" :: "r"(smem_dst), "l"(gsrc));
}
__device__ __forceinline__ void cp_commit() { asm volatile("cp.async.commit_group;\n"); }
__device__ __forceinline__ void cp_wait0()  { asm volatile("cp.async.wait_group 0;\n"); }

__device__ __forceinline__ unsigned f2tf32(float f) {
    unsigned r;
    asm("cvt.rna.tf32.f32 %0, %1;" : "=r"(r) : "f"(f));
    return r;
}
__device__ __forceinline__ float rtf(float f) { return __uint_as_float(f2tf32(f)); }

__device__ __forceinline__ void mma_tf32(float* c, const unsigned* a, const unsigned* b) {
    asm volatile(
        "mma.sync.aligned.m16n8k8.row.col.f32.tf32.tf32.f32 "
        "{%0,%1,%2,%3}, {%4,%5,%6,%7}, {%8,%9}, {%0,%1,%2,%3};\n"
        : "+f"(c[0]), "+f"(c[1]), "+f"(c[2]), "+f"(c[3])
        : "r"(a[0]), "r"(a[1]), "r"(a[2]), "r"(a[3]), "r"(b[0]), "r"(b[1]));
}

// ---------------------------------------------------------------------------
// Prep: tf32-round x, w_qkv, w_out into scratch (vectorized, grid-stride-free).
// total = (NX + NW1 + NW2)/4 = 3145728 float4 -> 12288 blocks x 256 threads.
// ---------------------------------------------------------------------------
__global__ __launch_bounds__(256)
void prep_tf32(const float* __restrict__ x,
               const float* __restrict__ wq,
               const float* __restrict__ wo)
{
    size_t i = (size_t)blockIdx.x * 256 + threadIdx.x;   // float4 index
    const size_t nx = NX / 4, nw1 = NW1 / 4;
    const float4* src;
    float4* dst;
    size_t j;
    if (i < nx)            { src = (const float4*)x;  dst = (float4*)g_x;  j = i; }
    else if (i < nx + nw1) { src = (const float4*)wq; dst = (float4*)g_w1; j = i - nx; }
    else                   { src = (const float4*)wo; dst = (float4*)g_w2; j = i - nx - nw1; }
    float4 v = src[j];
    v.x = rtf(v.x); v.y = rtf(v.y); v.z = rtf(v.z); v.w = rtf(v.w);
    dst[j] = v;
}

// ---------------------------------------------------------------------------
// TF32 tensor-core GEMM (NT): C[m,n] = sum_k A[m,k]*B[n,k].  M=8192, K=1024.
// Inputs already tf32-rounded -> inner loop is pure LDS + HMMA.
// QKV=true : A=g_x, B=g_w1, scatter tf32 into g_q (x0.125)/g_k/g_v; N=3072.
// QKV=false: A=g_o, B=g_w2, plain f32 store to Cout; N=1024.
// ---------------------------------------------------------------------------
#define KP 20   // padded k-stride

template<bool QKV>
__global__ __launch_bounds__(256)
void gemm_tc(float* __restrict__ Cout)
{
    __shared__ float As[2][128 * KP];
    __shared__ float Bs[2][128 * KP];

    const float* A = QKV ? g_x  : g_o;
    const float* B = QKV ? g_w1 : g_w2;

    const int tid  = threadIdx.x;
    const int lane = tid & 31;
    const int wid  = tid >> 5;
    const int wm   = wid >> 2;
    const int wn   = wid & 3;
    const int m0   = blockIdx.y << 7;
    const int n0   = blockIdx.x << 7;
    const int g    = lane >> 2;
    const int t    = lane & 3;

    float acc[4][4][4];
    #pragma unroll
    for (int i = 0; i < 4; ++i)
        #pragma unroll
        for (int j = 0; j < 4; ++j)
            #pragma unroll
            for (int r = 0; r < 4; ++r) acc[i][j][r] = 0.0f;

    const int lrow = tid >> 2;
    const int lcol = (tid & 3) << 2;
    const float* Ag = A + (size_t)(m0 + lrow) * 1024 + lcol;
    const float* Bg = B + (size_t)(n0 + lrow) * 1024 + lcol;

    const unsigned sA0 = (unsigned)__cvta_generic_to_shared(&As[0][lrow * KP + lcol]);
    const unsigned sB0 = (unsigned)__cvta_generic_to_shared(&Bs[0][lrow * KP + lcol]);
    const unsigned bufstride = 128 * KP * 4;
    const unsigned rowstride = 64 * KP * 4;

    cp_async16(sA0,             Ag);
    cp_async16(sA0 + rowstride, Ag + 64 * 1024);
    cp_async16(sB0,             Bg);
    cp_async16(sB0 + rowstride, Bg + 64 * 1024);
    cp_commit();
    cp_wait0();
    __syncthreads();

    int buf = 0;
    for (int kt = 0; kt < 64; ++kt) {
        if (kt + 1 < 64) {
            int k0 = (kt + 1) << 4;
            unsigned sA = sA0 + (unsigned)(buf ^ 1) * bufstride;
            unsigned sB = sB0 + (unsigned)(buf ^ 1) * bufstride;
            cp_async16(sA,             Ag + k0);
            cp_async16(sA + rowstride, Ag + 64 * 1024 + k0);
            cp_async16(sB,             Bg + k0);
            cp_async16(sB + rowstride, Bg + 64 * 1024 + k0);
            cp_commit();
        }

        const float* as = &As[buf][0];
        const float* bs = &Bs[buf][0];
        #pragma unroll
        for (int kk = 0; kk < 16; kk += 8) {
            unsigned af[4][4], bf[4][2];
            #pragma unroll
            for (int im = 0; im < 4; ++im) {
                const float* p = as + (wm * 64 + im * 16 + g) * KP + kk + t;
                af[im][0] = __float_as_uint(p[0]);
                af[im][1] = __float_as_uint(p[8 * KP]);
                af[im][2] = __float_as_uint(p[4]);
                af[im][3] = __float_as_uint(p[8 * KP + 4]);
            }
            #pragma unroll
            for (int jn = 0; jn < 4; ++jn) {
                const float* p = bs + (wn * 32 + jn * 8 + g) * KP + kk + t;
                bf[jn][0] = __float_as_uint(p[0]);
                bf[jn][1] = __float_as_uint(p[4]);
            }
            #pragma unroll
            for (int im = 0; im < 4; ++im)
                #pragma unroll
                for (int jn = 0; jn < 4; ++jn)
                    mma_tf32(acc[im][jn], af[im], bf[jn]);
        }

        cp_wait0();
        __syncthreads();
        buf ^= 1;
    }

    #pragma unroll
    for (int im = 0; im < 4; ++im) {
        #pragma unroll
        for (int jn = 0; jn < 4; ++jn) {
            int row = m0 + wm * 64 + im * 16 + g;
            int col = n0 + wn * 32 + jn * 8 + (t << 1);
            float2 v0 = make_float2(acc[im][jn][0], acc[im][jn][1]);
            float2 v1 = make_float2(acc[im][jn][2], acc[im][jn][3]);
            if (QKV) {
                int part = col >> 10;            // 0:q 1:k 2:v
                float sc = (part == 0) ? 0.125f : 1.0f;
                v0.x = rtf(v0.x * sc); v0.y = rtf(v0.y * sc);
                v1.x = rtf(v1.x * sc); v1.y = rtf(v1.y * sc);
                int nn   = col & 1023;
                int h    = nn >> 6;
                int d    = nn & 63;
                float* dst = (part == 0) ? g_q : ((part == 1) ? g_k : g_v);
                int bb = row >> 12, s = row & 4095;
                size_t base = (((size_t)(bb * NH + h)) * SEQ) * HD + d;
                *(float2*)(dst + base + (size_t)s * HD)       = v0;
                *(float2*)(dst + base + (size_t)(s + 8) * HD) = v1;
            } else {
                *(float2*)(Cout + (size_t)row * DM + col)       = v0;
                *(float2*)(Cout + (size_t)(row + 8) * DM + col) = v1;
            }
        }
    }
}

// ---------------------------------------------------------------------------
// Tensor-core flash attention. Block = 128 queries of one (b,h); 8 warps,
// warp w owns query rows [t0+16w, t0+16w+16). Key tiles of 64.
// allowed(q,k) = (k <= q) && (k < 16 || q-k < 512)
// ---------------------------------------------------------------------------
#define ST 68
#define SM_K 0
#define SM_V (64 * ST)
#define SM_Q (2 * 64 * ST)
#define SM_P (SM_Q + 128 * ST)
#define SM_TOT ((SM_P + 128 * ST) * 4)   // 104448 bytes

__global__ __launch_bounds__(256, 2)
void attn_tc()
{
    extern __shared__ float sm[];
    float* Ks = sm + SM_K;
    float* Vs = sm + SM_V;
    float* Qs = sm + SM_Q;
    float* Ps = sm + SM_P;

    const int tid  = threadIdx.x;
    const int lane = tid & 31;
    const int w    = tid >> 5;
    const int g    = lane >> 2;
    const int t    = lane & 3;
    const int bh   = blockIdx.y;
    const int t0   = blockIdx.x << 7;

    const float* Qg = g_q + (size_t)bh * SEQ * HD + (size_t)t0 * HD;
    const float* Kg = g_k + (size_t)bh * SEQ * HD;
    const float* Vg = g_v + (size_t)bh * SEQ * HD;

    #pragma unroll
    for (int it = 0; it < 8; ++it) {
        int idx = tid + (it << 8);
        int row = idx >> 4;
        int c4  = (idx & 15) << 2;
        *(float4*)&Qs[row * ST + c4] = *(const float4*)(Qg + row * 64 + c4);
    }

    const int rmin = t0 + w * 16;      // warp's min query row
    const int r0 = rmin + g;
    const int r1 = r0 + 8;

    float oa[8][4];
    #pragma unroll
    for (int j = 0; j < 8; ++j)
        #pragma unroll
        for (int r = 0; r < 4; ++r) oa[j][r] = 0.0f;
    float m0 = -1e30f, m1 = -1e30f, l0 = 0.0f, l1 = 0.0f;

    int lo = t0 - (WINDOW - 1); if (lo < 0) lo = 0;
    const int lo_tile = lo >> 6;
    const int hi_tile = (t0 + 127) >> 6;
    const int extra   = (lo_tile > 0) ? 1 : 0;
    const int ntiles  = hi_tile - lo_tile + 1 + extra;

    const int prow = (w * 16 + g) * ST;
    const int qrow = prow;

    for (int it = 0; it < ntiles; ++it) {
        int kt = extra ? ((it == 0) ? 0 : (lo_tile + it - 1)) : (lo_tile + it);
        int kbase = kt << 6;

        __syncthreads();
        #pragma unroll
        for (int it2 = 0; it2 < 4; ++it2) {
            int idx = tid + (it2 << 8);
            int row = idx >> 4;
            int c4  = (idx & 15) << 2;
            *(float4*)&Ks[row * ST + c4] = *(const float4*)(Kg + (size_t)(kbase + row) * 64 + c4);
            *(float4*)&Vs[row * ST + c4] = *(const float4*)(Vg + (size_t)(kbase + row) * 64 + c4);
        }
        __syncthreads();

        // S = Q K^T : warp computes 16 x 64
        float sc[8][4];
        #pragma unroll
        for (int j = 0; j < 8; ++j)
            #pragma unroll
            for (int r = 0; r < 4; ++r) sc[j][r] = 0.0f;

        #pragma unroll
        for (int kk = 0; kk < 8; ++kk) {
            unsigned qa[4];
            const float* qp = &Qs[qrow + kk * 8 + t];
            qa[0] = __float_as_uint(qp[0]);
            qa[1] = __float_as_uint(qp[8 * ST]);
            qa[2] = __float_as_uint(qp[4]);
            qa[3] = __float_as_uint(qp[8 * ST + 4]);
            #pragma unroll
            for (int j = 0; j < 8; ++j) {
                unsigned bb[2];
                const float* kp = &Ks[(j * 8 + g) * ST + kk * 8 + t];
                bb[0] = __float_as_uint(kp[0]);
                bb[1] = __float_as_uint(kp[4]);
                mma_tf32(sc[j], qa, bb);
            }
        }

        // Mask (skipped when warp's tile is fully unmasked) + row max
        const bool full = (kbase + 63 <= rmin) && ((rmin + 15 - kbase) < WINDOW);
        float rmax0 = -1e30f, rmax1 = -1e30f;
        if (!full) {
            #pragma unroll
            for (int j = 0; j < 8; ++j) {
                int kc0 = kbase + j * 8 + (t << 1);
                int kc1 = kc0 + 1;
                bool a00 = (kc0 <= r0) && ((kc0 < PREFIX) || ((r0 - kc0) < WINDOW));
                bool a01 = (kc1 <= r0) && ((kc1 < PREFIX) || ((r0 - kc1) < WINDOW));
                bool a10 = (kc0 <= r1) && ((kc0 < PREFIX) || ((r1 - kc0) < WINDOW));
                bool a11 = (kc1 <= r1) && ((kc1 < PREFIX) || ((r1 - kc1) < WINDOW));
                if (!a00) sc[j][0] = -1e30f;
                if (!a01) sc[j][1] = -1e30f;
                if (!a10) sc[j][2] = -1e30f;
                if (!a11) sc[j][3] = -1e30f;
            }
        }
        #pragma unroll
        for (int j = 0; j < 8; ++j) {
            rmax0 = fmaxf(rmax0, fmaxf(sc[j][0], sc[j][1]));
            rmax1 = fmaxf(rmax1, fmaxf(sc[j][2], sc[j][3]));
        }
        rmax0 = fmaxf(rmax0, __shfl_xor_sync(0xffffffffu, rmax0, 1));
        rmax0 = fmaxf(rmax0, __shfl_xor_sync(0xffffffffu, rmax0, 2));
        rmax1 = fmaxf(rmax1, __shfl_xor_sync(0xffffffffu, rmax1, 1));
        rmax1 = fmaxf(rmax1, __shfl_xor_sync(0xffffffffu, rmax1, 2));

        float mn0 = fmaxf(fmaxf(m0, rmax0), -1e28f);
        float mn1 = fmaxf(fmaxf(m1, rmax1), -1e28f);
        float esc0 = __expf(m0 - mn0);
        float esc1 = __expf(m1 - mn1);

        float rs0 = 0.0f, rs1 = 0.0f;
        #pragma unroll
        for (int j = 0; j < 8; ++j) {
            float p0 = __expf(sc[j][0] - mn0);
            float p1 = __expf(sc[j][1] - mn0);
            float p2 = __expf(sc[j][2] - mn1);
            float p3 = __expf(sc[j][3] - mn1);
            rs0 += p0 + p1;
            rs1 += p2 + p3;
            int col = j * 8 + (t << 1);
            *(float2*)&Ps[prow + col]          = make_float2(rtf(p0), rtf(p1));
            *(float2*)&Ps[prow + 8 * ST + col] = make_float2(rtf(p2), rtf(p3));
        }
        rs0 += __shfl_xor_sync(0xffffffffu, rs0, 1);
        rs0 += __shfl_xor_sync(0xffffffffu, rs0, 2);
        rs1 += __shfl_xor_sync(0xffffffffu, rs1, 1);
        rs1 += __shfl_xor_sync(0xffffffffu, rs1, 2);

        l0 = l0 * esc0 + rs0;
        l1 = l1 * esc1 + rs1;
        m0 = mn0;
        m1 = mn1;
        #pragma unroll
        for (int j = 0; j < 8; ++j) {
            oa[j][0] *= esc0; oa[j][1] *= esc0;
            oa[j][2] *= esc1; oa[j][3] *= esc1;
        }
        __syncwarp();

        // O += P V : warp computes 16 x 64
        #pragma unroll
        for (int kk = 0; kk < 8; ++kk) {
            unsigned pa[4];
            const float* pp = &Ps[prow + kk * 8 + t];
            pa[0] = __float_as_uint(pp[0]);
            pa[1] = __float_as_uint(pp[8 * ST]);
            pa[2] = __float_as_uint(pp[4]);
            pa[3] = __float_as_uint(pp[8 * ST + 4]);
            #pragma unroll
            for (int j = 0; j < 8; ++j) {
                unsigned bb[2];
                const float* vp = &Vs[(kk * 8 + t) * ST + j * 8 + g];
                bb[0] = __float_as_uint(vp[0]);
                bb[1] = __float_as_uint(vp[4 * ST]);
                mma_tf32(oa[j], pa, bb);
            }
        }
    }

    // Finalize: g_o[b][s][h*64+d], tf32-rounded for the out-proj GEMM
    const int b = bh >> 4, h = bh & 15;
    const float inv0 = 1.0f / l0;
    const float inv1 = 1.0f / l1;
    float* d0 = g_o + ((size_t)b * SEQ + r0) * DM + h * HD;
    float* d1 = g_o + ((size_t)b * SEQ + r1) * DM + h * HD;
    #pragma unroll
    for (int j = 0; j < 8; ++j) {
        int col = j * 8 + (t << 1);
        *(float2*)&d0[col] = make_float2(rtf(oa[j][0] * inv0), rtf(oa[j][1] * inv0));
        *(float2*)&d1[col] = make_float2(rtf(oa[j][2] * inv1), rtf(oa[j][3] * inv1));
    }
}

// ---------------------------------------------------------------------------
extern "C" void kernel_launch(void* const* d_in, const int* in_sizes, int n_in,
                              void* d_out, int out_size)
{
    const float* x     = (const float*)d_in[0];
    const float* w_qkv = (const float*)d_in[1];
    const float* w_out = (const float*)d_in[2];
    float* out = (float*)d_out;

    cudaFuncSetAttribute(attn_tc, cudaFuncAttributeMaxDynamicSharedMemorySize, SM_TOT);

    // 0) tf32-round all GEMM inputs once
    prep_tf32<<<(unsigned)((NX + NW1 + NW2) / 4 / 256), 256>>>(x, w_qkv, w_out);
    // 1) QKV projection (cvt-free TF32 tensor cores), scatter into [bh][s][d]
    gemm_tc<true><<<dim3(3072 / 128, 8192 / 128), 256>>>(nullptr);
    // 2) tensor-core flash attention -> g_o (tf32)
    attn_tc<<<dim3(SEQ / 128, BATCH * NH), 256, SM_TOT>>>();
    // 3) output projection -> d_out (f32)
    gemm_tc<false><<<dim3(1024 / 128, 8192 / 128), 256>>>(out);
}

// round 7
// speedup vs baseline: 1.1742x; 1.1742x over previous
#include <cuda_runtime.h>
#include <cstdint>

#define WINDOW   512
#define PREFIX   16
#define SEQ      4096
#define NH       16
#define BATCH    2
#define DM       1024
#define HD       64

#define NX  ((size_t)BATCH * SEQ * DM)
#define NW1 ((size_t)3 * DM * DM)
#define NW2 ((size_t)DM * DM)

// Scratch (device globals; allocation APIs are forbidden).
__device__ float g_q[(size_t)BATCH * NH * SEQ * HD];   // tf32, pre-scaled 1/8
__device__ float g_k[(size_t)BATCH * NH * SEQ * HD];   // tf32
__device__ float g_v[(size_t)BATCH * NH * SEQ * HD];   // tf32
__device__ float g_o[(size_t)BATCH * SEQ * DM];        // tf32 [b][s][h*64+d]
__device__ float g_x[NX];                              // tf32 copy of x
__device__ float g_w1[NW1];                            // tf32 copy of w_qkv
__device__ float g_w2[NW2];                            // tf32 copy of w_out

// ---------------------------------------------------------------------------
__device__ __forceinline__ void cp_async16(unsigned smem_dst, const void* gsrc) {
    asm volatile("cp.async.cg.shared.global [%0], [%1], 16;\n" :: "r"(smem_dst), "l"(gsrc));
}
__device__ __forceinline__ void cp_commit() { asm volatile("cp.async.commit_group;\n"); }
__device__ __forceinline__ void cp_wait0()  { asm volatile("cp.async.wait_group 0;\n"); }

__device__ __forceinline__ unsigned f2tf32(float f) {
    unsigned r;
    asm("cvt.rna.tf32.f32 %0, %1;" : "=r"(r) : "f"(f));
    return r;
}
__device__ __forceinline__ float rtf(float f) { return __uint_as_float(f2tf32(f)); }

__device__ __forceinline__ void mma_tf32(float* c, const unsigned* a, const unsigned* b) {
    asm volatile(
        "mma.sync.aligned.m16n8k8.row.col.f32.tf32.tf32.f32 "
        "{%0,%1,%2,%3}, {%4,%5,%6,%7}, {%8,%9}, {%0,%1,%2,%3};\n"
        : "+f"(c[0]), "+f"(c[1]), "+f"(c[2]), "+f"(c[3])
        : "r"(a[0]), "r"(a[1]), "r"(a[2]), "r"(a[3]), "r"(b[0]), "r"(b[1]));
}

// ---------------------------------------------------------------------------
// Prep: tf32-round x, w_qkv, w_out into scratch.
// ---------------------------------------------------------------------------
__global__ __launch_bounds__(256)
void prep_tf32(const float* __restrict__ x,
               const float* __restrict__ wq,
               const float* __restrict__ wo)
{
    size_t i = (size_t)blockIdx.x * 256 + threadIdx.x;
    const size_t nx = NX / 4, nw1 = NW1 / 4;
    const float4* src;
    float4* dst;
    size_t j;
    if (i < nx)            { src = (const float4*)x;  dst = (float4*)g_x;  j = i; }
    else if (i < nx + nw1) { src = (const float4*)wq; dst = (float4*)g_w1; j = i - nx; }
    else                   { src = (const float4*)wo; dst = (float4*)g_w2; j = i - nx - nw1; }
    float4 v = src[j];
    v.x = rtf(v.x); v.y = rtf(v.y); v.z = rtf(v.z); v.w = rtf(v.w);
    dst[j] = v;
}

// ---------------------------------------------------------------------------
// TF32 tensor-core GEMM (NT), latency-optimized:
//  - 32-deep k-tiles (half the barrier count)
//  - register double-buffered fragments (LDS of group i+1 overlaps MMA of i)
// Block 128x128, warp tile 64x32. Dynamic smem: 2 stages x (A+B) x 128x36.
// ---------------------------------------------------------------------------
#define KT  32
#define KP2 36
#define GEMM_SMEM (2 * 2 * 128 * KP2 * 4)   // 73728 bytes

template<bool QKV>
__global__ __launch_bounds__(256, 2)
void gemm_tc(float* __restrict__ Cout)
{
    extern __shared__ float smem[];
    float* Asm = smem;                       // [2][128*KP2]
    float* Bsm = smem + 2 * 128 * KP2;

    const float* A = QKV ? g_x  : g_o;
    const float* B = QKV ? g_w1 : g_w2;

    const int tid  = threadIdx.x;
    const int lane = tid & 31;
    const int wid  = tid >> 5;
    const int wm   = wid >> 2;
    const int wn   = wid & 3;
    const int m0   = blockIdx.y << 7;
    const int n0   = blockIdx.x << 7;
    const int g    = lane >> 2;
    const int t    = lane & 3;

    float acc[4][4][4];
    #pragma unroll
    for (int i = 0; i < 4; ++i)
        #pragma unroll
        for (int j = 0; j < 4; ++j)
            #pragma unroll
            for (int r = 0; r < 4; ++r) acc[i][j][r] = 0.0f;

    const unsigned sA = (unsigned)__cvta_generic_to_shared(Asm);
    const unsigned sB = (unsigned)__cvta_generic_to_shared(Bsm);
    const unsigned stg = 128 * KP2 * 4;      // bytes per stage

    // staging: 1024 float4 per matrix per tile -> 4 per thread per matrix
    #define GSTAGE(k0, s)                                                        \
        do {                                                                     \
            _Pragma("unroll")                                                    \
            for (int it2 = 0; it2 < 4; ++it2) {                                  \
                int idx = tid + (it2 << 8);                                      \
                int row = idx >> 3;                                              \
                int c4  = (idx & 7) << 2;                                        \
                unsigned off = (unsigned)(row * KP2 + c4) * 4 + (s) * stg;       \
                cp_async16(sA + off, A + (size_t)(m0 + row) * 1024 + (k0) + c4); \
                cp_async16(sB + off, B + (size_t)(n0 + row) * 1024 + (k0) + c4); \
            }                                                                    \
            cp_commit();                                                         \
        } while (0)

    #define GLOADF(kq, b, as, bs)                                                \
        do {                                                                     \
            _Pragma("unroll")                                                    \
            for (int im = 0; im < 4; ++im) {                                     \
                const float* p = (as) + (wm * 64 + im * 16 + g) * KP2 + (kq) * 8 + t; \
                af[b][im][0] = __float_as_uint(p[0]);                            \
                af[b][im][1] = __float_as_uint(p[8 * KP2]);                      \
                af[b][im][2] = __float_as_uint(p[4]);                            \
                af[b][im][3] = __float_as_uint(p[8 * KP2 + 4]);                  \
            }                                                                    \
            _Pragma("unroll")                                                    \
            for (int jn = 0; jn < 4; ++jn) {                                     \
                const float* p = (bs) + (wn * 32 + jn * 8 + g) * KP2 + (kq) * 8 + t; \
                bf[b][jn][0] = __float_as_uint(p[0]);                            \
                bf[b][jn][1] = __float_as_uint(p[4]);                            \
            }                                                                    \
        } while (0)

    GSTAGE(0, 0);
    cp_wait0();
    __syncthreads();

    int buf = 0;
    for (int kt = 0; kt < 1024 / KT; ++kt) {
        if (kt + 1 < 1024 / KT) GSTAGE((kt + 1) * KT, buf ^ 1);

        const float* as = Asm + buf * 128 * KP2;
        const float* bs = Bsm + buf * 128 * KP2;

        unsigned af[2][4][4], bf[2][4][2];
        GLOADF(0, 0, as, bs);
        #pragma unroll
        for (int kq = 0; kq < 4; ++kq) {
            int cur = kq & 1;
            if (kq < 3) GLOADF(kq + 1, cur ^ 1, as, bs);
            #pragma unroll
            for (int im = 0; im < 4; ++im)
                #pragma unroll
                for (int jn = 0; jn < 4; ++jn)
                    mma_tf32(acc[im][jn], af[cur][im], bf[cur][jn]);
        }

        cp_wait0();
        __syncthreads();
        buf ^= 1;
    }

    #pragma unroll
    for (int im = 0; im < 4; ++im) {
        #pragma unroll
        for (int jn = 0; jn < 4; ++jn) {
            int row = m0 + wm * 64 + im * 16 + g;
            int col = n0 + wn * 32 + jn * 8 + (t << 1);
            float2 v0 = make_float2(acc[im][jn][0], acc[im][jn][1]);
            float2 v1 = make_float2(acc[im][jn][2], acc[im][jn][3]);
            if (QKV) {
                int part = col >> 10;            // 0:q 1:k 2:v
                float sc = (part == 0) ? 0.125f : 1.0f;
                v0.x = rtf(v0.x * sc); v0.y = rtf(v0.y * sc);
                v1.x = rtf(v1.x * sc); v1.y = rtf(v1.y * sc);
                int nn   = col & 1023;
                int h    = nn >> 6;
                int d    = nn & 63;
                float* dst = (part == 0) ? g_q : ((part == 1) ? g_k : g_v);
                int bb = row >> 12, s = row & 4095;
                size_t base = (((size_t)(bb * NH + h)) * SEQ) * HD + d;
                *(float2*)(dst + base + (size_t)s * HD)       = v0;
                *(float2*)(dst + base + (size_t)(s + 8) * HD) = v1;
            } else {
                *(float2*)(Cout + (size_t)row * DM + col)       = v0;
                *(float2*)(Cout + (size_t)(row + 8) * DM + col) = v1;
            }
        }
    }
    #undef GSTAGE
    #undef GLOADF
}

// ---------------------------------------------------------------------------
// Tensor-core flash attention, latency-optimized:
//  - Q fragments live in registers (loaded once from gmem; warp-private rows)
//  - K/V double-buffered via cp.async: next tile load overlaps compute
// Block = 128 queries; 8 warps; warp w owns rows [t0+16w, t0+16w+16).
// ---------------------------------------------------------------------------
#define ST 68
#define SM_P (4 * 64 * ST)
#define SM_TOT ((SM_P + 128 * ST) * 4)   // 104448 bytes

__global__ __launch_bounds__(256, 2)
void attn_tc()
{
    extern __shared__ float sm[];
    // K buf0 | K buf1 | V buf0 | V buf1 | P
    float* Ps = sm + SM_P;

    const int tid  = threadIdx.x;
    const int lane = tid & 31;
    const int w    = tid >> 5;
    const int g    = lane >> 2;
    const int t    = lane & 3;
    const int bh   = blockIdx.y;
    const int t0   = blockIdx.x << 7;

    const float* Kg = g_k + (size_t)bh * SEQ * HD;
    const float* Vg = g_v + (size_t)bh * SEQ * HD;

    const unsigned sbase = (unsigned)__cvta_generic_to_shared(sm);
    const unsigned kvstg = 64 * ST * 4;

    // Q fragments in registers: rows r0 = t0+16w+g, r1 = r0+8.
    const int rmin = t0 + w * 16;
    const int r0 = rmin + g;
    const int r1 = r0 + 8;
    unsigned qa[8][4];
    {
        const float* q0 = g_q + (size_t)bh * SEQ * HD + (size_t)r0 * HD;
        #pragma unroll
        for (int kk = 0; kk < 8; ++kk) {
            qa[kk][0] = __float_as_uint(q0[kk * 8 + t]);
            qa[kk][1] = __float_as_uint(q0[512 + kk * 8 + t]);      // +8 rows
            qa[kk][2] = __float_as_uint(q0[kk * 8 + t + 4]);
            qa[kk][3] = __float_as_uint(q0[512 + kk * 8 + t + 4]);
        }
    }

    #define ASTAGE(kbase, s)                                                     \
        do {                                                                     \
            _Pragma("unroll")                                                    \
            for (int it2 = 0; it2 < 4; ++it2) {                                  \
                int idx = tid + (it2 << 8);                                      \
                int row = idx >> 4;                                              \
                int c4  = (idx & 15) << 2;                                       \
                unsigned off = (unsigned)(row * ST + c4) * 4 + (s) * kvstg;      \
                cp_async16(sbase + off,               Kg + (size_t)((kbase) + row) * 64 + c4); \
                cp_async16(sbase + off + 2 * kvstg,   Vg + (size_t)((kbase) + row) * 64 + c4); \
            }                                                                    \
            cp_commit();                                                         \
        } while (0)

    float oa[8][4];
    #pragma unroll
    for (int j = 0; j < 8; ++j)
        #pragma unroll
        for (int r = 0; r < 4; ++r) oa[j][r] = 0.0f;
    float m0 = -1e30f, m1 = -1e30f, l0 = 0.0f, l1 = 0.0f;

    int lo = t0 - (WINDOW - 1); if (lo < 0) lo = 0;
    const int lo_tile = lo >> 6;
    const int hi_tile = (t0 + 127) >> 6;
    const int extra   = (lo_tile > 0) ? 1 : 0;
    const int ntiles  = hi_tile - lo_tile + 1 + extra;

    const int prow = (w * 16 + g) * ST;

    // tile index -> kbase
    #define KBASE(i) ((extra ? (((i) == 0) ? 0 : (lo_tile + (i) - 1)) : (lo_tile + (i))) << 6)

    ASTAGE(KBASE(0), 0);

    int buf = 0;
    for (int it = 0; it < ntiles; ++it) {
        const int kbase = KBASE(it);
        cp_wait0();
        __syncthreads();                       // tile `it` resident in buf
        if (it + 1 < ntiles) ASTAGE(KBASE(it + 1), buf ^ 1);

        const float* Ks = sm + buf * 64 * ST;
        const float* Vs = sm + (2 + buf) * 64 * ST;

        // S = Q K^T : 16 x 64 per warp
        float sc[8][4];
        #pragma unroll
        for (int j = 0; j < 8; ++j)
            #pragma unroll
            for (int r = 0; r < 4; ++r) sc[j][r] = 0.0f;

        #pragma unroll
        for (int kk = 0; kk < 8; ++kk) {
            #pragma unroll
            for (int j = 0; j < 8; ++j) {
                unsigned bb[2];
                const float* kp = &Ks[(j * 8 + g) * ST + kk * 8 + t];
                bb[0] = __float_as_uint(kp[0]);
                bb[1] = __float_as_uint(kp[4]);
                mma_tf32(sc[j], qa[kk], bb);
            }
        }

        // Mask (skipped for fully-unmasked warp tiles) + row max
        const bool full = (kbase + 63 <= rmin) && ((rmin + 15 - kbase) < WINDOW);
        if (!full) {
            #pragma unroll
            for (int j = 0; j < 8; ++j) {
                int kc0 = kbase + j * 8 + (t << 1);
                int kc1 = kc0 + 1;
                bool a00 = (kc0 <= r0) && ((kc0 < PREFIX) || ((r0 - kc0) < WINDOW));
                bool a01 = (kc1 <= r0) && ((kc1 < PREFIX) || ((r0 - kc1) < WINDOW));
                bool a10 = (kc0 <= r1) && ((kc0 < PREFIX) || ((r1 - kc0) < WINDOW));
                bool a11 = (kc1 <= r1) && ((kc1 < PREFIX) || ((r1 - kc1) < WINDOW));
                if (!a00) sc[j][0] = -1e30f;
                if (!a01) sc[j][1] = -1e30f;
                if (!a10) sc[j][2] = -1e30f;
                if (!a11) sc[j][3] = -1e30f;
            }
        }
        float rmax0 = -1e30f, rmax1 = -1e30f;
        #pragma unroll
        for (int j = 0; j < 8; ++j) {
            rmax0 = fmaxf(rmax0, fmaxf(sc[j][0], sc[j][1]));
            rmax1 = fmaxf(rmax1, fmaxf(sc[j][2], sc[j][3]));
        }
        rmax0 = fmaxf(rmax0, __shfl_xor_sync(0xffffffffu, rmax0, 1));
        rmax0 = fmaxf(rmax0, __shfl_xor_sync(0xffffffffu, rmax0, 2));
        rmax1 = fmaxf(rmax1, __shfl_xor_sync(0xffffffffu, rmax1, 1));
        rmax1 = fmaxf(rmax1, __shfl_xor_sync(0xffffffffu, rmax1, 2));

        float mn0 = fmaxf(fmaxf(m0, rmax0), -1e28f);
        float mn1 = fmaxf(fmaxf(m1, rmax1), -1e28f);
        float esc0 = __expf(m0 - mn0);
        float esc1 = __expf(m1 - mn1);

        float rs0 = 0.0f, rs1 = 0.0f;
        #pragma unroll
        for (int j = 0; j < 8; ++j) {
            float p0 = __expf(sc[j][0] - mn0);
            float p1 = __expf(sc[j][1] - mn0);
            float p2 = __expf(sc[j][2] - mn1);
            float p3 = __expf(sc[j][3] - mn1);
            rs0 += p0 + p1;
            rs1 += p2 + p3;
            int col = j * 8 + (t << 1);
            *(float2*)&Ps[prow + col]          = make_float2(rtf(p0), rtf(p1));
            *(float2*)&Ps[prow + 8 * ST + col] = make_float2(rtf(p2), rtf(p3));
        }
        rs0 += __shfl_xor_sync(0xffffffffu, rs0, 1);
        rs0 += __shfl_xor_sync(0xffffffffu, rs0, 2);
        rs1 += __shfl_xor_sync(0xffffffffu, rs1, 1);
        rs1 += __shfl_xor_sync(0xffffffffu, rs1, 2);

        l0 = l0 * esc0 + rs0;
        l1 = l1 * esc1 + rs1;
        m0 = mn0;
        m1 = mn1;
        #pragma unroll
        for (int j = 0; j < 8; ++j) {
            oa[j][0] *= esc0; oa[j][1] *= esc0;
            oa[j][2] *= esc1; oa[j][3] *= esc1;
        }
        __syncwarp();                           // P rows are warp-private

        // O += P V : 16 x 64 per warp
        #pragma unroll
        for (int kk = 0; kk < 8; ++kk) {
            unsigned pa[4];
            const float* pp = &Ps[prow + kk * 8 + t];
            pa[0] = __float_as_uint(pp[0]);
            pa[1] = __float_as_uint(pp[8 * ST]);
            pa[2] = __float_as_uint(pp[4]);
            pa[3] = __float_as_uint(pp[8 * ST + 4]);
            #pragma unroll
            for (int j = 0; j < 8; ++j) {
                unsigned bb[2];
                const float* vp = &Vs[(kk * 8 + t) * ST + j * 8 + g];
                bb[0] = __float_as_uint(vp[0]);
                bb[1] = __float_as_uint(vp[4 * ST]);
                mma_tf32(oa[j], pa, bb);
            }
        }
        buf ^= 1;
    }

    // Finalize: g_o[b][s][h*64+d], tf32-rounded for the out-proj GEMM
    const int b = bh >> 4, h = bh & 15;
    const float inv0 = 1.0f / l0;
    const float inv1 = 1.0f / l1;
    float* d0 = g_o + ((size_t)b * SEQ + r0) * DM + h * HD;
    float* d1 = g_o + ((size_t)b * SEQ + r1) * DM + h * HD;
    #pragma unroll
    for (int j = 0; j < 8; ++j) {
        int col = j * 8 + (t << 1);
        *(float2*)&d0[col] = make_float2(rtf(oa[j][0] * inv0), rtf(oa[j][1] * inv0));
        *(float2*)&d1[col] = make_float2(rtf(oa[j][2] * inv1), rtf(oa[j][3] * inv1));
    }
    #undef ASTAGE
    #undef KBASE
}

// ---------------------------------------------------------------------------
extern "C" void kernel_launch(void* const* d_in, const int* in_sizes, int n_in,
                              void* d_out, int out_size)
{
    const float* x     = (const float*)d_in[0];
    const float* w_qkv = (const float*)d_in[1];
    const float* w_out = (const float*)d_in[2];
    float* out = (float*)d_out;

    cudaFuncSetAttribute(gemm_tc<true>,  cudaFuncAttributeMaxDynamicSharedMemorySize, GEMM_SMEM);
    cudaFuncSetAttribute(gemm_tc<false>, cudaFuncAttributeMaxDynamicSharedMemorySize, GEMM_SMEM);
    cudaFuncSetAttribute(attn_tc,        cudaFuncAttributeMaxDynamicSharedMemorySize, SM_TOT);

    // 0) tf32-round all GEMM inputs once
    prep_tf32<<<(unsigned)((NX + NW1 + NW2) / 4 / 256), 256>>>(x, w_qkv, w_out);
    // 1) QKV projection -> g_q/g_k/g_v
    gemm_tc<true><<<dim3(3072 / 128, 8192 / 128), 256, GEMM_SMEM>>>(nullptr);
    // 2) tensor-core flash attention -> g_o (tf32)
    attn_tc<<<dim3(SEQ / 128, BATCH * NH), 256, SM_TOT>>>();
    // 3) output projection -> d_out (f32)
    gemm_tc<false><<<dim3(1024 / 128, 8192 / 128), 256, GEMM_SMEM>>>(out);
}

// round 8
// speedup vs baseline: 1.3589x; 1.1573x over previous
#include <cuda_runtime.h>
#include <cstdint>

#define WINDOW   512
#define PREFIX   16
#define SEQ      4096
#define NH       16
#define BATCH    2
#define DM       1024
#define HD       64

#define NX  ((size_t)BATCH * SEQ * DM)
#define NW1 ((size_t)3 * DM * DM)
#define NW2 ((size_t)DM * DM)

// Scratch (device globals; allocation APIs are forbidden).
__device__ float g_q [(size_t)BATCH * NH * SEQ * HD];  // tf32, pre-scaled 1/8, [bh][s][d]
__device__ float g_k [(size_t)BATCH * NH * SEQ * HD];  // tf32, [bh][s][d]
__device__ float g_vt[(size_t)BATCH * NH * HD * SEQ];  // tf32, TRANSPOSED [bh][d][s]
__device__ float g_o [(size_t)BATCH * SEQ * DM];       // tf32 [b][s][h*64+d]
__device__ float g_x [NX];                             // tf32 copy of x
__device__ float g_w1[NW1];                            // tf32 copy of w_qkv
__device__ float g_w2[NW2];                            // tf32 copy of w_out

// ---------------------------------------------------------------------------
__device__ __forceinline__ void cp_async16(unsigned smem_dst, const void* gsrc) {
    asm volatile("cp.async.cg.shared.global [%0], [%1], 16;\n" :: "r"(smem_dst), "l"(gsrc));
}
__device__ __forceinline__ void cp_commit() { asm volatile("cp.async.commit_group;\n"); }
__device__ __forceinline__ void cp_wait0()  { asm volatile("cp.async.wait_group 0;\n"); }

__device__ __forceinline__ unsigned f2tf32(float f) {
    unsigned r;
    asm("cvt.rna.tf32.f32 %0, %1;" : "=r"(r) : "f"(f));
    return r;
}
__device__ __forceinline__ float rtf(float f) { return __uint_as_float(f2tf32(f)); }

__device__ __forceinline__ void mma_tf32(float* c, const unsigned* a, const unsigned* b) {
    asm volatile(
        "mma.sync.aligned.m16n8k8.row.col.f32.tf32.tf32.f32 "
        "{%0,%1,%2,%3}, {%4,%5,%6,%7}, {%8,%9}, {%0,%1,%2,%3};\n"
        : "+f"(c[0]), "+f"(c[1]), "+f"(c[2]), "+f"(c[3])
        : "r"(a[0]), "r"(a[1]), "r"(a[2]), "r"(a[3]), "r"(b[0]), "r"(b[1]));
}

// ldmatrix x4: lane L receives 32-bit word (L%4) of row (L/4) of each matrix.
__device__ __forceinline__ void ldsm4(unsigned& r0, unsigned& r1, unsigned& r2, unsigned& r3,
                                      unsigned addr) {
    asm volatile("ldmatrix.sync.aligned.m8n8.x4.shared.b16 {%0,%1,%2,%3}, [%4];"
                 : "=r"(r0), "=r"(r1), "=r"(r2), "=r"(r3) : "r"(addr));
}

// ---------------------------------------------------------------------------
// Prep: tf32-round x, w_qkv, w_out into scratch.
// ---------------------------------------------------------------------------
__global__ __launch_bounds__(256)
void prep_tf32(const float* __restrict__ x,
               const float* __restrict__ wq,
               const float* __restrict__ wo)
{
    size_t i = (size_t)blockIdx.x * 256 + threadIdx.x;
    const size_t nx = NX / 4, nw1 = NW1 / 4;
    const float4* src;
    float4* dst;
    size_t j;
    if (i < nx)            { src = (const float4*)x;  dst = (float4*)g_x;  j = i; }
    else if (i < nx + nw1) { src = (const float4*)wq; dst = (float4*)g_w1; j = i - nx; }
    else                   { src = (const float4*)wo; dst = (float4*)g_w2; j = i - nx - nw1; }
    float4 v = src[j];
    v.x = rtf(v.x); v.y = rtf(v.y); v.z = rtf(v.z); v.w = rtf(v.w);
    dst[j] = v;
}

// ---------------------------------------------------------------------------
// TF32 tensor-core GEMM (NT), ldmatrix operand loads.
// Block 128x128, 8 warps (2x4), warp tile 64x32, 32-deep double-buffered k-tiles.
// ---------------------------------------------------------------------------
#define KT  32
#define KP2 36
#define GEMM_SMEM (2 * 2 * 128 * KP2 * 4)   // 73728 bytes

template<bool QKV>
__global__ __launch_bounds__(256, 2)
void gemm_tc(float* __restrict__ Cout)
{
    extern __shared__ float smem[];
    float* Asm = smem;                       // [2][128*KP2]
    float* Bsm = smem + 2 * 128 * KP2;

    const float* A = QKV ? g_x  : g_o;
    const float* B = QKV ? g_w1 : g_w2;

    const int tid  = threadIdx.x;
    const int lane = tid & 31;
    const int wid  = tid >> 5;
    const int wm   = wid >> 2;
    const int wn   = wid & 3;
    const int m0   = blockIdx.y << 7;
    const int n0   = blockIdx.x << 7;
    const int g    = lane >> 2;
    const int t    = lane & 3;
    const int r8   = lane & 7;
    const int sel  = lane >> 3;              // 0..3: which 8x8 matrix this lane addresses

    float acc[4][4][4];
    #pragma unroll
    for (int i = 0; i < 4; ++i)
        #pragma unroll
        for (int j = 0; j < 4; ++j)
            #pragma unroll
            for (int r = 0; r < 4; ++r) acc[i][j][r] = 0.0f;

    const unsigned sA = (unsigned)__cvta_generic_to_shared(Asm);
    const unsigned sB = (unsigned)__cvta_generic_to_shared(Bsm);
    const unsigned stg = 128 * KP2 * 4;      // bytes per stage

    // ldmatrix per-lane base addresses (byte offsets into stage 0):
    // A m16k8 tile: m0=(r+0,k0-3) m1=(r+8,k0-3) m2=(r+0,k4-7) m3=(r+8,k4-7)
    const unsigned aLd = sA + (unsigned)(((wm * 64 + ((sel & 1) << 3) + r8) * KP2
                                          + ((sel >> 1) << 2)) << 2);
    // B n8-pair: m0=(jn0,k0-3) m1=(jn0,k4-7) m2=(jn1,k0-3) m3=(jn1,k4-7)
    const unsigned bLd = sB + (unsigned)(((wn * 32 + ((sel >> 1) << 3) + r8) * KP2
                                          + ((sel & 1) << 2)) << 2);

    #define GSTAGE(k0, s)                                                        \
        do {                                                                     \
            _Pragma("unroll")                                                    \
            for (int it2 = 0; it2 < 4; ++it2) {                                  \
                int idx = tid + (it2 << 8);                                      \
                int row = idx >> 3;                                              \
                int c4  = (idx & 7) << 2;                                        \
                unsigned off = (unsigned)(row * KP2 + c4) * 4 + (s) * stg;       \
                cp_async16(sA + off, A + (size_t)(m0 + row) * 1024 + (k0) + c4); \
                cp_async16(sB + off, B + (size_t)(n0 + row) * 1024 + (k0) + c4); \
            }                                                                    \
            cp_commit();                                                         \
        } while (0)

    GSTAGE(0, 0);
    cp_wait0();
    __syncthreads();

    int buf = 0;
    for (int kt = 0; kt < 1024 / KT; ++kt) {
        if (kt + 1 < 1024 / KT) GSTAGE((kt + 1) * KT, buf ^ 1);

        const unsigned boff = (unsigned)buf * stg;
        #pragma unroll
        for (int kq = 0; kq < 4; ++kq) {
            unsigned af[4][4];
            #pragma unroll
            for (int im = 0; im < 4; ++im)
                ldsm4(af[im][0], af[im][1], af[im][2], af[im][3],
                      aLd + boff + (unsigned)(im * 16 * KP2 * 4) + (unsigned)(kq * 32));
            #pragma unroll
            for (int p = 0; p < 2; ++p) {
                unsigned b0[2], b1[2];
                ldsm4(b0[0], b0[1], b1[0], b1[1],
                      bLd + boff + (unsigned)(p * 16 * KP2 * 4) + (unsigned)(kq * 32));
                #pragma unroll
                for (int im = 0; im < 4; ++im) {
                    mma_tf32(acc[im][2 * p],     af[im], b0);
                    mma_tf32(acc[im][2 * p + 1], af[im], b1);
                }
            }
        }

        cp_wait0();
        __syncthreads();
        buf ^= 1;
    }

    #pragma unroll
    for (int im = 0; im < 4; ++im) {
        #pragma unroll
        for (int jn = 0; jn < 4; ++jn) {
            int row = m0 + wm * 64 + im * 16 + g;
            int col = n0 + wn * 32 + jn * 8 + (t << 1);
            float2 v0 = make_float2(acc[im][jn][0], acc[im][jn][1]);
            float2 v1 = make_float2(acc[im][jn][2], acc[im][jn][3]);
            if (QKV) {
                int part = col >> 10;            // 0:q 1:k 2:v
                float sc = (part == 0) ? 0.125f : 1.0f;
                v0.x = rtf(v0.x * sc); v0.y = rtf(v0.y * sc);
                v1.x = rtf(v1.x * sc); v1.y = rtf(v1.y * sc);
                int nn = col & 1023;
                int h  = nn >> 6;
                int d  = nn & 63;
                int bb = row >> 12, s = row & 4095;
                if (part == 2) {
                    // transposed: g_vt[bh][d][s]
                    float* dst = g_vt + ((size_t)(bb * NH + h) * HD + d) * SEQ + s;
                    dst[0]       = v0.x;
                    dst[SEQ]     = v0.y;
                    dst[8]       = v1.x;
                    dst[SEQ + 8] = v1.y;
                } else {
                    float* dst = (part == 0) ? g_q : g_k;
                    size_t base = (((size_t)(bb * NH + h)) * SEQ) * HD + d;
                    *(float2*)(dst + base + (size_t)s * HD)       = v0;
                    *(float2*)(dst + base + (size_t)(s + 8) * HD) = v1;
                }
            } else {
                *(float2*)(Cout + (size_t)row * DM + col)       = v0;
                *(float2*)(Cout + (size_t)(row + 8) * DM + col) = v1;
            }
        }
    }
    #undef GSTAGE
}

// ---------------------------------------------------------------------------
// Tensor-core flash attention: Q in registers, cp.async double-buffered K/V^T,
// all MMA operands via ldmatrix.
// Block = 128 queries; 8 warps; warp w owns rows [t0+16w, t0+16w+16).
// ---------------------------------------------------------------------------
#define ST 68
#define SM_P (4 * 64 * ST)
#define SM_TOT ((SM_P + 128 * ST) * 4)   // 104448 bytes

__global__ __launch_bounds__(256, 2)
void attn_tc()
{
    extern __shared__ float sm[];
    // K buf0 | K buf1 | Vt buf0 | Vt buf1 | P
    float* Ps = sm + SM_P;

    const int tid  = threadIdx.x;
    const int lane = tid & 31;
    const int w    = tid >> 5;
    const int g    = lane >> 2;
    const int t    = lane & 3;
    const int r8   = lane & 7;
    const int sel  = lane >> 3;
    const int bh   = blockIdx.y;
    const int t0   = blockIdx.x << 7;

    const float* Kg  = g_k  + (size_t)bh * SEQ * HD;
    const float* Vtg = g_vt + (size_t)bh * HD * SEQ;

    const unsigned sbase = (unsigned)__cvta_generic_to_shared(sm);
    const unsigned kvstg = 64 * ST * 4;

    // ldmatrix base addresses:
    // K/Vt (B-frag, j-pair): m0=(j0,k0-3) m1=(j0,k4-7) m2=(j1,k0-3) m3=(j1,k4-7)
    const unsigned kLd = sbase + (unsigned)(((((sel >> 1) << 3) + r8) * ST
                                             + ((sel & 1) << 2)) << 2);
    const unsigned vLd = kLd + 2 * kvstg;
    // P (A-frag): m0=(r+0,k0-3) m1=(r+8,k0-3) m2=(r+0,k4-7) m3=(r+8,k4-7)
    const unsigned pLd = sbase + (unsigned)SM_P * 4
                       + (unsigned)(((w * 16 + ((sel & 1) << 3) + r8) * ST
                                     + ((sel >> 1) << 2)) << 2);

    // Q fragments in registers: rows r0 = t0+16w+g, r1 = r0+8.
    const int rmin = t0 + w * 16;
    const int r0 = rmin + g;
    const int r1 = r0 + 8;
    unsigned qa[8][4];
    {
        const float* q0 = g_q + (size_t)bh * SEQ * HD + (size_t)r0 * HD;
        #pragma unroll
        for (int kk = 0; kk < 8; ++kk) {
            qa[kk][0] = __float_as_uint(q0[kk * 8 + t]);
            qa[kk][1] = __float_as_uint(q0[512 + kk * 8 + t]);
            qa[kk][2] = __float_as_uint(q0[kk * 8 + t + 4]);
            qa[kk][3] = __float_as_uint(q0[512 + kk * 8 + t + 4]);
        }
    }

    // Stage K tile (rows=key, cols=d) and Vt tile (rows=d, cols=key)
    #define ASTAGE(kbase, s)                                                     \
        do {                                                                     \
            _Pragma("unroll")                                                    \
            for (int it2 = 0; it2 < 4; ++it2) {                                  \
                int idx = tid + (it2 << 8);                                      \
                int row = idx >> 4;                                              \
                int c4  = (idx & 15) << 2;                                       \
                unsigned off = (unsigned)(row * ST + c4) * 4 + (s) * kvstg;      \
                cp_async16(sbase + off,             Kg  + (size_t)((kbase) + row) * 64 + c4); \
                cp_async16(sbase + off + 2 * kvstg, Vtg + (size_t)row * SEQ + (kbase) + c4);  \
            }                                                                    \
            cp_commit();                                                         \
        } while (0)

    float oa[8][4];
    #pragma unroll
    for (int j = 0; j < 8; ++j)
        #pragma unroll
        for (int r = 0; r < 4; ++r) oa[j][r] = 0.0f;
    float m0 = -1e30f, m1 = -1e30f, l0 = 0.0f, l1 = 0.0f;

    int lo = t0 - (WINDOW - 1); if (lo < 0) lo = 0;
    const int lo_tile = lo >> 6;
    const int hi_tile = (t0 + 127) >> 6;
    const int extra   = (lo_tile > 0) ? 1 : 0;
    const int ntiles  = hi_tile - lo_tile + 1 + extra;

    const int prow = (w * 16 + g) * ST;

    #define KBASE(i) ((extra ? (((i) == 0) ? 0 : (lo_tile + (i) - 1)) : (lo_tile + (i))) << 6)

    ASTAGE(KBASE(0), 0);

    int buf = 0;
    for (int it = 0; it < ntiles; ++it) {
        const int kbase = KBASE(it);
        cp_wait0();
        __syncthreads();
        if (it + 1 < ntiles) ASTAGE(KBASE(it + 1), buf ^ 1);

        const unsigned boff = (unsigned)buf * kvstg;

        // S = Q K^T : 16 x 64 per warp
        float sc[8][4];
        #pragma unroll
        for (int j = 0; j < 8; ++j)
            #pragma unroll
            for (int r = 0; r < 4; ++r) sc[j][r] = 0.0f;

        #pragma unroll
        for (int kk = 0; kk < 8; ++kk) {
            #pragma unroll
            for (int p = 0; p < 4; ++p) {
                unsigned b0[2], b1[2];
                ldsm4(b0[0], b0[1], b1[0], b1[1],
                      kLd + boff + (unsigned)(p * 16 * ST * 4) + (unsigned)(kk * 32));
                mma_tf32(sc[2 * p],     qa[kk], b0);
                mma_tf32(sc[2 * p + 1], qa[kk], b1);
            }
        }

        // Mask (skipped for fully-unmasked warp tiles) + row max
        const bool full = (kbase + 63 <= rmin) && ((rmin + 15 - kbase) < WINDOW);
        if (!full) {
            #pragma unroll
            for (int j = 0; j < 8; ++j) {
                int kc0 = kbase + j * 8 + (t << 1);
                int kc1 = kc0 + 1;
                bool a00 = (kc0 <= r0) && ((kc0 < PREFIX) || ((r0 - kc0) < WINDOW));
                bool a01 = (kc1 <= r0) && ((kc1 < PREFIX) || ((r0 - kc1) < WINDOW));
                bool a10 = (kc0 <= r1) && ((kc0 < PREFIX) || ((r1 - kc0) < WINDOW));
                bool a11 = (kc1 <= r1) && ((kc1 < PREFIX) || ((r1 - kc1) < WINDOW));
                if (!a00) sc[j][0] = -1e30f;
                if (!a01) sc[j][1] = -1e30f;
                if (!a10) sc[j][2] = -1e30f;
                if (!a11) sc[j][3] = -1e30f;
            }
        }
        float rmax0 = -1e30f, rmax1 = -1e30f;
        #pragma unroll
        for (int j = 0; j < 8; ++j) {
            rmax0 = fmaxf(rmax0, fmaxf(sc[j][0], sc[j][1]));
            rmax1 = fmaxf(rmax1, fmaxf(sc[j][2], sc[j][3]));
        }
        rmax0 = fmaxf(rmax0, __shfl_xor_sync(0xffffffffu, rmax0, 1));
        rmax0 = fmaxf(rmax0, __shfl_xor_sync(0xffffffffu, rmax0, 2));
        rmax1 = fmaxf(rmax1, __shfl_xor_sync(0xffffffffu, rmax1, 1));
        rmax1 = fmaxf(rmax1, __shfl_xor_sync(0xffffffffu, rmax1, 2));

        float mn0 = fmaxf(fmaxf(m0, rmax0), -1e28f);
        float mn1 = fmaxf(fmaxf(m1, rmax1), -1e28f);
        float esc0 = __expf(m0 - mn0);
        float esc1 = __expf(m1 - mn1);

        float rs0 = 0.0f, rs1 = 0.0f;
        #pragma unroll
        for (int j = 0; j < 8; ++j) {
            float p0 = __expf(sc[j][0] - mn0);
            float p1 = __expf(sc[j][1] - mn0);
            float p2 = __expf(sc[j][2] - mn1);
            float p3 = __expf(sc[j][3] - mn1);
            rs0 += p0 + p1;
            rs1 += p2 + p3;
            int col = j * 8 + (t << 1);
            *(float2*)&Ps[prow + col]          = make_float2(rtf(p0), rtf(p1));
            *(float2*)&Ps[prow + 8 * ST + col] = make_float2(rtf(p2), rtf(p3));
        }
        rs0 += __shfl_xor_sync(0xffffffffu, rs0, 1);
        rs0 += __shfl_xor_sync(0xffffffffu, rs0, 2);
        rs1 += __shfl_xor_sync(0xffffffffu, rs1, 1);
        rs1 += __shfl_xor_sync(0xffffffffu, rs1, 2);

        l0 = l0 * esc0 + rs0;
        l1 = l1 * esc1 + rs1;
        m0 = mn0;
        m1 = mn1;
        #pragma unroll
        for (int j = 0; j < 8; ++j) {
            oa[j][0] *= esc0; oa[j][1] *= esc0;
            oa[j][2] *= esc1; oa[j][3] *= esc1;
        }
        __syncwarp();                           // P rows are warp-private

        // O += P V : 16 x 64 per warp (B-frags from transposed V tile)
        #pragma unroll
        for (int kk = 0; kk < 8; ++kk) {
            unsigned pa[4];
            ldsm4(pa[0], pa[1], pa[2], pa[3], pLd + (unsigned)(kk * 32));
            #pragma unroll
            for (int p = 0; p < 4; ++p) {
                unsigned b0[2], b1[2];
                ldsm4(b0[0], b0[1], b1[0], b1[1],
                      vLd + boff + (unsigned)(p * 16 * ST * 4) + (unsigned)(kk * 32));
                mma_tf32(oa[2 * p],     pa, b0);
                mma_tf32(oa[2 * p + 1], pa, b1);
            }
        }
        buf ^= 1;
    }

    // Finalize: g_o[b][s][h*64+d], tf32-rounded for the out-proj GEMM
    const int b = bh >> 4, h = bh & 15;
    const float inv0 = 1.0f / l0;
    const float inv1 = 1.0f / l1;
    float* d0 = g_o + ((size_t)b * SEQ + r0) * DM + h * HD;
    float* d1 = g_o + ((size_t)b * SEQ + r1) * DM + h * HD;
    #pragma unroll
    for (int j = 0; j < 8; ++j) {
        int col = j * 8 + (t << 1);
        *(float2*)&d0[col] = make_float2(rtf(oa[j][0] * inv0), rtf(oa[j][1] * inv0));
        *(float2*)&d1[col] = make_float2(rtf(oa[j][2] * inv1), rtf(oa[j][3] * inv1));
    }
    #undef ASTAGE
    #undef KBASE
}

// ---------------------------------------------------------------------------
extern "C" void kernel_launch(void* const* d_in, const int* in_sizes, int n_in,
                              void* d_out, int out_size)
{
    const float* x     = (const float*)d_in[0];
    const float* w_qkv = (const float*)d_in[1];
    const float* w_out = (const float*)d_in[2];
    float* out = (float*)d_out;

    cudaFuncSetAttribute(gemm_tc<true>,  cudaFuncAttributeMaxDynamicSharedMemorySize, GEMM_SMEM);
    cudaFuncSetAttribute(gemm_tc<false>, cudaFuncAttributeMaxDynamicSharedMemorySize, GEMM_SMEM);
    cudaFuncSetAttribute(attn_tc,        cudaFuncAttributeMaxDynamicSharedMemorySize, SM_TOT);

    // 0) tf32-round all GEMM inputs once
    prep_tf32<<<(unsigned)((NX + NW1 + NW2) / 4 / 256), 256>>>(x, w_qkv, w_out);
    // 1) QKV projection -> g_q/g_k/g_vt (v transposed)
    gemm_tc<true><<<dim3(3072 / 128, 8192 / 128), 256, GEMM_SMEM>>>(nullptr);
    // 2) tensor-core flash attention -> g_o (tf32)
    attn_tc<<<dim3(SEQ / 128, BATCH * NH), 256, SM_TOT>>>();
    // 3) output projection -> d_out (f32)
    gemm_tc<false><<<dim3(1024 / 128, 8192 / 128), 256, GEMM_SMEM>>>(out);
}